// round 4
// baseline (speedup 1.0000x reference)
#include <cuda_runtime.h>
#include <cstdint>

#define S 8192
#define H 1024
#define NSM 128
#define SCAN_THREADS 512
#define NREP 4          // tag replicas (distinct L2 slices)

// Scratch: input-side gate projections gx[S][3H].
__device__ float g_gx[(size_t)S * 3 * H];
// Per-producer monotone tags: g_tags[rep][chunk][64] (only first 32 used per
// chunk; 64-int = 256B chunk stride so chunks land on distinct L2 slices).
__device__ unsigned int g_tags[NREP * 4 * 64];

// ---------------------------------------------------------------------------
// packed fp32x2 helpers (sm_103a FFMA2 path)
// ---------------------------------------------------------------------------
__device__ __forceinline__ unsigned long long pack2(float lo, float hi) {
    unsigned long long r;
    asm("mov.b64 %0, {%1, %2};" : "=l"(r) : "f"(lo), "f"(hi));
    return r;
}
__device__ __forceinline__ unsigned long long ffma2(unsigned long long a,
                                                    unsigned long long b,
                                                    unsigned long long c) {
    unsigned long long d;
    asm("fma.rn.f32x2 %0, %1, %2, %3;" : "=l"(d) : "l"(a), "l"(b), "l"(c));
    return d;
}
__device__ __forceinline__ float hsum2(unsigned long long a) {
    float lo, hi;
    asm("mov.b64 {%0, %1}, %2;" : "=f"(lo), "=f"(hi) : "l"(a));
    return lo + hi;
}

// ---------------------------------------------------------------------------
// Kernel 1: gx = inp @ W_ih^T + b_ih  (fp32 GEMM, 128x128x16 tiles, FFMA2)
// Block 0 also clears the tag array so each graph replay starts clean.
// ---------------------------------------------------------------------------
__global__ __launch_bounds__(256) void gemm_gx_kernel(
    const float* __restrict__ A,
    const float* __restrict__ Wih,
    const float* __restrict__ bih)
{
    __shared__ __align__(16) float As[16][132];
    __shared__ __align__(16) float Bs[16][132];

    const int tid = threadIdx.x;
    if (blockIdx.x == 0 && blockIdx.y == 0) {
#pragma unroll
        for (int q = 0; q < 4; ++q)
            g_tags[tid * 4 + q] = 0u;
    }

    const int m0 = blockIdx.y * 128;
    const int n0 = blockIdx.x * 128;
    const int tx = tid & 15;
    const int ty = tid >> 4;

    unsigned long long acc2[8][4];
#pragma unroll
    for (int i = 0; i < 8; ++i)
#pragma unroll
        for (int q = 0; q < 4; ++q) acc2[i][q] = 0ULL;

    for (int kt = 0; kt < 1024; kt += 16) {
#pragma unroll
        for (int r = 0; r < 2; ++r) {
            int idx = tid + r * 256;
            int row = idx >> 2;
            int kq  = idx & 3;
            float4 v = *(const float4*)(A + (size_t)(m0 + row) * 1024 + kt + kq * 4);
            As[kq * 4 + 0][row] = v.x;
            As[kq * 4 + 1][row] = v.y;
            As[kq * 4 + 2][row] = v.z;
            As[kq * 4 + 3][row] = v.w;
        }
#pragma unroll
        for (int r = 0; r < 2; ++r) {
            int idx = tid + r * 256;
            int n  = idx >> 2;
            int kq = idx & 3;
            float4 v = *(const float4*)(Wih + (size_t)(n0 + n) * 1024 + kt + kq * 4);
            Bs[kq * 4 + 0][n] = v.x;
            Bs[kq * 4 + 1][n] = v.y;
            Bs[kq * 4 + 2][n] = v.z;
            Bs[kq * 4 + 3][n] = v.w;
        }
        __syncthreads();

#pragma unroll
        for (int k = 0; k < 16; ++k) {
            float4 b0 = *(const float4*)&Bs[k][tx * 8];
            float4 b1 = *(const float4*)&Bs[k][tx * 8 + 4];
            unsigned long long rb2[4];
            rb2[0] = pack2(b0.x, b0.y);
            rb2[1] = pack2(b0.z, b0.w);
            rb2[2] = pack2(b1.x, b1.y);
            rb2[3] = pack2(b1.z, b1.w);
#pragma unroll
            for (int i = 0; i < 8; ++i) {
                float a = As[k][ty * 8 + i];
                unsigned long long a2 = pack2(a, a);
#pragma unroll
                for (int q = 0; q < 4; ++q)
                    acc2[i][q] = ffma2(a2, rb2[q], acc2[i][q]);
            }
        }
        __syncthreads();
    }

#pragma unroll
    for (int i = 0; i < 8; ++i) {
        size_t rowoff = (size_t)(m0 + ty * 8 + i) * 3072 + n0 + tx * 8;
#pragma unroll
        for (int jq = 0; jq < 2; ++jq) {
            float lo0, hi0, lo1, hi1;
            asm("mov.b64 {%0, %1}, %2;" : "=f"(lo0), "=f"(hi0) : "l"(acc2[i][jq * 2 + 0]));
            asm("mov.b64 {%0, %1}, %2;" : "=f"(lo1), "=f"(hi1) : "l"(acc2[i][jq * 2 + 1]));
            float4 v;
            v.x = lo0 + bih[n0 + tx * 8 + jq * 4 + 0];
            v.y = hi0 + bih[n0 + tx * 8 + jq * 4 + 1];
            v.z = lo1 + bih[n0 + tx * 8 + jq * 4 + 2];
            v.w = hi1 + bih[n0 + tx * 8 + jq * 4 + 3];
            *(float4*)(g_gx + rowoff + jq * 4) = v;
        }
    }
}

// ---------------------------------------------------------------------------
// Kernel 2: persistent GRU scan. 128 CTAs (one per SM), 512 threads.
// Each CTA owns 8 output dims => 24 gate-rows of W_hh in registers (f32x2).
// h_t lives in d_out (L2 exchange). Sync:
//   producers: lane0 threadfence + 4 replicated relaxed tag stores (value t+1)
//   consumers: ONE poller warp per k-chunk (warps 4..7) polls the 32 producer
//              tags of its chunk with a single coalesced relaxed LDG + ballot,
//              then relays to sibling warps through volatile smem.
// partials are double-buffered on t&1 so no trailing barrier is needed.
// ---------------------------------------------------------------------------
__global__ __launch_bounds__(SCAN_THREADS, 1) void gru_scan_kernel(
    const float* __restrict__ Whh,
    const float* __restrict__ bhh,
    float* __restrict__ out)
{
    const int tid  = threadIdx.x;
    const int warp = tid >> 5;
    const int lane = tid & 31;
    const int c = warp & 3;        // k-chunk id (0..3)
    const int g = warp >> 2;       // row-group id (0..3)
    const int bid = blockIdx.x;
    const int obase = bid * 8;
    const int k0 = c * 256 + lane * 8;
    const int gb   = bid >> 5;     // this CTA's producer chunk-group
    const int slot = bid & 31;     // slot within the group

    __shared__ __align__(16) float partials[2][24][36];
    __shared__ int s_ready[4];     // relay: last step whose h is available+rep

    if (tid < 4) s_ready[tid] = 0;

    // --- preload 6 gate-rows x 8 cols of W_hh, packed as f32x2 ---
    unsigned long long w2[6][4];
#pragma unroll
    for (int j = 0; j < 6; ++j) {
        int gr  = g * 6 + j;                          // 0..23
        int row = (gr >> 3) * H + obase + (gr & 7);   // gate*H + output index
        const float4* p = (const float4*)(Whh + (size_t)row * H + k0);
        float4 a = p[0], b = p[1];
        w2[j][0] = pack2(a.x, a.y);
        w2[j][1] = pack2(a.z, a.w);
        w2[j][2] = pack2(b.x, b.y);
        w2[j][3] = pack2(b.z, b.w);
    }

    const bool isw0 = (warp == 0);
    const bool ispoller = (warp >= 4 && warp < 8);   // poller for chunk (warp-4)==c
    const int o = lane & 7;
    float bh = 0.f;
    if (isw0 && lane < 24) bh = bhh[(lane >> 3) * H + obase + o];
    float hprev = 0.f;            // lanes 0..7 of warp 0 carry h for their dim

    const size_t gx_lane_off = (size_t)(lane >> 3) * H + obase + o;
    // poller's tag address: replica bid&3, chunk c, producer index = lane
    const unsigned int* tagp = &g_tags[(((unsigned)bid & 3) * 4 + c) * 64 + lane];
    volatile int* vready = s_ready;

    __syncthreads();

    for (int t = 0; t < S; ++t) {
        const int buf = t & 1;

        // prefetch gx for this step (independent of the wait)
        float gxv = 0.f;
        if (isw0 && lane < 24)
            gxv = g_gx[(size_t)t * (3 * H) + gx_lane_off];

        unsigned long long h2[4];
        if (t == 0) {
#pragma unroll
            for (int q = 0; q < 4; ++q) h2[q] = 0ULL;
        } else {
            if (ispoller) {
                // poll 32 producer tags of chunk c in one coalesced LDG
                unsigned int v;
                do {
                    asm volatile("ld.relaxed.gpu.global.u32 %0, [%1];"
                                 : "=r"(v) : "l"(tagp) : "memory");
                } while (__any_sync(0xFFFFFFFFu, v < (unsigned)t));
                asm volatile("fence.acq_rel.gpu;" ::: "memory");
                if (lane == 0) vready[c] = t;
            } else {
                if (lane == 0) { while (vready[c] < t) { } }
                __syncwarp();
            }
            const float4* hp = (const float4*)(out + (size_t)(t - 1) * H + k0);
            float4 a = hp[0], b = hp[1];
            h2[0] = pack2(a.x, a.y);
            h2[1] = pack2(a.z, a.w);
            h2[2] = pack2(b.x, b.y);
            h2[3] = pack2(b.z, b.w);
        }

        // --- packed partial dots: 6 rows x 4 f32x2 FMAs ---
        float accv[6];
#pragma unroll
        for (int j = 0; j < 6; ++j) {
            unsigned long long acc = 0ULL;
#pragma unroll
            for (int q = 0; q < 4; ++q) acc = ffma2(w2[j][q], h2[q], acc);
            accv[j] = hsum2(acc);
        }

        // --- 2 shuffle rounds: 32 lanes -> 8 representatives ---
#pragma unroll
        for (int j = 0; j < 6; ++j) {
            accv[j] += __shfl_xor_sync(0xFFFFFFFFu, accv[j], 16);
            accv[j] += __shfl_xor_sync(0xFFFFFFFFu, accv[j], 8);
        }
        if (lane < 8) {
#pragma unroll
            for (int j = 0; j < 6; ++j)
                partials[buf][g * 6 + j][c * 8 + lane] = accv[j];
        }
        __syncthreads();   // partials(buf) complete

        // --- finalize: warp 0, one lane per gate-row (24 lanes) ---
        if (isw0) {
            float val = 0.f;
            if (lane < 24) {
                const float4* pr = (const float4*)(&partials[buf][lane][0]);
                float4 p0 = pr[0], p1 = pr[1], p2 = pr[2], p3 = pr[3];
                float4 p4 = pr[4], p5 = pr[5], p6 = pr[6], p7 = pr[7];
                float4 q0, q1, q2, q3, r0, r1, f;
                q0.x = p0.x + p1.x; q0.y = p0.y + p1.y; q0.z = p0.z + p1.z; q0.w = p0.w + p1.w;
                q1.x = p2.x + p3.x; q1.y = p2.y + p3.y; q1.z = p2.z + p3.z; q1.w = p2.w + p3.w;
                q2.x = p4.x + p5.x; q2.y = p4.y + p5.y; q2.z = p4.z + p5.z; q2.w = p4.w + p5.w;
                q3.x = p6.x + p7.x; q3.y = p6.y + p7.y; q3.z = p6.z + p7.z; q3.w = p6.w + p7.w;
                r0.x = q0.x + q1.x; r0.y = q0.y + q1.y; r0.z = q0.z + q1.z; r0.w = q0.w + q1.w;
                r1.x = q2.x + q3.x; r1.y = q2.y + q3.y; r1.z = q2.z + q3.z; r1.w = q2.w + q3.w;
                f.x = r0.x + r1.x; f.y = r0.y + r1.y; f.z = r0.z + r1.z; f.w = r0.w + r1.w;
                float s = bh + ((f.x + f.y) + (f.z + f.w));
                val = (lane < 16) ? (s + gxv) : s;   // r/z fold gx; n keeps split
            }
            float v_z  = __shfl_sync(0xFFFFFFFFu, val, o + 8);
            float v_n  = __shfl_sync(0xFFFFFFFFu, val, o + 16);
            float gx_n = __shfl_sync(0xFFFFFFFFu, gxv, o + 16);
            if (lane < 8) {
                float er = __expf(-val);
                float r  = __fdividef(1.f, 1.f + er);
                float ez = __expf(-v_z);
                float z  = __fdividef(1.f, 1.f + ez);
                float a  = gx_n + r * v_n;
                float e2 = __expf(2.f * a);
                float n  = 1.f - __fdividef(2.f, e2 + 1.f);   // tanh(a)
                float hn = z * (hprev - n) + n;               // (1-z)*n + z*h
                hprev = hn;
                out[(size_t)t * H + obase + o] = hn;
            }
            __syncwarp();
            if (lane == 0) {
                __threadfence();   // release: h STGs visible before tags
#pragma unroll
                for (int rep = 0; rep < NREP; ++rep) {
                    unsigned int* tp = &g_tags[(rep * 4 + gb) * 64 + slot];
                    asm volatile("st.relaxed.gpu.global.u32 [%0], %1;"
                                 :: "l"(tp), "r"((unsigned)(t + 1)) : "memory");
                }
            }
        }
        // no trailing barrier: partials are double-buffered, and iteration
        // t+1's writes are gated by tags that require this CTA's publish.
    }
}

// ---------------------------------------------------------------------------
extern "C" void kernel_launch(void* const* d_in, const int* in_sizes, int n_in,
                              void* d_out, int out_size)
{
    const float* inp  = (const float*)d_in[0];  // [8192, 1024]
    const float* W_ih = (const float*)d_in[1];  // [3072, 1024]
    const float* W_hh = (const float*)d_in[2];  // [3072, 1024]
    const float* b_ih = (const float*)d_in[3];  // [3072]
    const float* b_hh = (const float*)d_in[4];  // [3072]
    float* out = (float*)d_out;                 // [8192, 1024]

    // 1) gx = inp @ W_ih^T + b_ih (block 0 also clears g_tags for this replay)
    dim3 ggrid(3072 / 128, S / 128);
    gemm_gx_kernel<<<ggrid, 256>>>(inp, W_ih, b_ih);

    // 2) persistent sequential GRU scan (one wave of 128 CTAs)
    gru_scan_kernel<<<NSM, SCAN_THREADS>>>(W_hh, b_hh, out);
}

// round 5
// speedup vs baseline: 1.2644x; 1.2644x over previous
#include <cuda_runtime.h>
#include <cstdint>

#define S 8192
#define H 1024
#define NSM 128
#define SCAN_THREADS 544   // 16 dot-warps + 1 poller/finalizer warp (warp 16)
#define TAG_STRIDE 8       // uints between per-CTA tags (32B -> sector each)

// Scratch: input-side gate projections gx[S][3H] and per-CTA monotone tags.
__device__ float g_gx[(size_t)S * 3 * H];
__device__ unsigned int g_tags[NSM * TAG_STRIDE];

// ---------------------------------------------------------------------------
// packed fp32x2 helpers (sm_103a FFMA2 path)
// ---------------------------------------------------------------------------
__device__ __forceinline__ unsigned long long pack2(float lo, float hi) {
    unsigned long long r;
    asm("mov.b64 %0, {%1, %2};" : "=l"(r) : "f"(lo), "f"(hi));
    return r;
}
__device__ __forceinline__ unsigned long long ffma2(unsigned long long a,
                                                    unsigned long long b,
                                                    unsigned long long c) {
    unsigned long long d;
    asm("fma.rn.f32x2 %0, %1, %2, %3;" : "=l"(d) : "l"(a), "l"(b), "l"(c));
    return d;
}
__device__ __forceinline__ float hsum2(unsigned long long a) {
    float lo, hi;
    asm("mov.b64 {%0, %1}, %2;" : "=f"(lo), "=f"(hi) : "l"(a));
    return lo + hi;
}

// ---------------------------------------------------------------------------
// Kernel 1: gx = inp @ W_ih^T + b_ih  (fp32 GEMM, 128x128x16 tiles, FFMA2)
// Block (0,0) also clears the tag array so each graph replay starts clean.
// ---------------------------------------------------------------------------
__global__ __launch_bounds__(256) void gemm_gx_kernel(
    const float* __restrict__ A,
    const float* __restrict__ Wih,
    const float* __restrict__ bih)
{
    __shared__ __align__(16) float As[16][132];
    __shared__ __align__(16) float Bs[16][132];

    const int tid = threadIdx.x;
    if (blockIdx.x == 0 && blockIdx.y == 0) {
#pragma unroll
        for (int q = 0; q < 4; ++q)
            g_tags[tid * 4 + q] = 0u;
    }

    const int m0 = blockIdx.y * 128;
    const int n0 = blockIdx.x * 128;
    const int tx = tid & 15;
    const int ty = tid >> 4;

    unsigned long long acc2[8][4];
#pragma unroll
    for (int i = 0; i < 8; ++i)
#pragma unroll
        for (int q = 0; q < 4; ++q) acc2[i][q] = 0ULL;

    for (int kt = 0; kt < 1024; kt += 16) {
#pragma unroll
        for (int r = 0; r < 2; ++r) {
            int idx = tid + r * 256;
            int row = idx >> 2;
            int kq  = idx & 3;
            float4 v = *(const float4*)(A + (size_t)(m0 + row) * 1024 + kt + kq * 4);
            As[kq * 4 + 0][row] = v.x;
            As[kq * 4 + 1][row] = v.y;
            As[kq * 4 + 2][row] = v.z;
            As[kq * 4 + 3][row] = v.w;
        }
#pragma unroll
        for (int r = 0; r < 2; ++r) {
            int idx = tid + r * 256;
            int n  = idx >> 2;
            int kq = idx & 3;
            float4 v = *(const float4*)(Wih + (size_t)(n0 + n) * 1024 + kt + kq * 4);
            Bs[kq * 4 + 0][n] = v.x;
            Bs[kq * 4 + 1][n] = v.y;
            Bs[kq * 4 + 2][n] = v.z;
            Bs[kq * 4 + 3][n] = v.w;
        }
        __syncthreads();

#pragma unroll
        for (int k = 0; k < 16; ++k) {
            float4 b0 = *(const float4*)&Bs[k][tx * 8];
            float4 b1 = *(const float4*)&Bs[k][tx * 8 + 4];
            unsigned long long rb2[4];
            rb2[0] = pack2(b0.x, b0.y);
            rb2[1] = pack2(b0.z, b0.w);
            rb2[2] = pack2(b1.x, b1.y);
            rb2[3] = pack2(b1.z, b1.w);
#pragma unroll
            for (int i = 0; i < 8; ++i) {
                float a = As[k][ty * 8 + i];
                unsigned long long a2 = pack2(a, a);
#pragma unroll
                for (int q = 0; q < 4; ++q)
                    acc2[i][q] = ffma2(a2, rb2[q], acc2[i][q]);
            }
        }
        __syncthreads();
    }

#pragma unroll
    for (int i = 0; i < 8; ++i) {
        size_t rowoff = (size_t)(m0 + ty * 8 + i) * 3072 + n0 + tx * 8;
#pragma unroll
        for (int jq = 0; jq < 2; ++jq) {
            float lo0, hi0, lo1, hi1;
            asm("mov.b64 {%0, %1}, %2;" : "=f"(lo0), "=f"(hi0) : "l"(acc2[i][jq * 2 + 0]));
            asm("mov.b64 {%0, %1}, %2;" : "=f"(lo1), "=f"(hi1) : "l"(acc2[i][jq * 2 + 1]));
            float4 v;
            v.x = lo0 + bih[n0 + tx * 8 + jq * 4 + 0];
            v.y = hi0 + bih[n0 + tx * 8 + jq * 4 + 1];
            v.z = lo1 + bih[n0 + tx * 8 + jq * 4 + 2];
            v.w = hi1 + bih[n0 + tx * 8 + jq * 4 + 3];
            *(float4*)(g_gx + rowoff + jq * 4) = v;
        }
    }
}

// ---------------------------------------------------------------------------
// Kernel 2: persistent GRU scan. 128 CTAs (one per SM), 544 threads.
// Warps 0..15: dot warps (4 k-chunks x 4 row-groups), 24 gate-rows of W_hh
//              register-resident as packed f32x2. Parked at __syncthreads
//              while waiting (no spin -> no arbiter pollution).
// Warp 16:     poller + finalizer (highest wid -> highest arbiter priority).
//              Polls all 128 per-CTA tags with 4 acquire-LDGs/lane, releases
//              the CTA barrier, later finalizes gates and publishes its tag
//              with a single st.release (NO atomics -> no LTS serialization).
// h_t lives in d_out (L2 exchange). Single-buffer partials, 2 bars/step.
// ---------------------------------------------------------------------------
__global__ __launch_bounds__(SCAN_THREADS, 1) void gru_scan_kernel(
    const float* __restrict__ Whh,
    const float* __restrict__ bhh,
    float* __restrict__ out)
{
    const int tid  = threadIdx.x;
    const int warp = tid >> 5;
    const int lane = tid & 31;
    const int bid  = blockIdx.x;
    const int obase = bid * 8;

    __shared__ __align__(16) float partials[24][36];

    const bool isdot = (warp < 16);
    const bool isfin = (warp == 16);

    // ---- dot-warp setup ----
    const int c = warp & 3;              // k-chunk (0..3)
    const int g = warp >> 2;             // row-group (0..3)
    const int k0 = c * 256 + lane * 8;

    unsigned long long w2[6][4];
    if (isdot) {
#pragma unroll
        for (int j = 0; j < 6; ++j) {
            int gr  = g * 6 + j;                          // 0..23
            int row = (gr >> 3) * H + obase + (gr & 7);   // gate*H + out idx
            const float4* p = (const float4*)(Whh + (size_t)row * H + k0);
            float4 a = p[0], b = p[1];
            w2[j][0] = pack2(a.x, a.y);
            w2[j][1] = pack2(a.z, a.w);
            w2[j][2] = pack2(b.x, b.y);
            w2[j][3] = pack2(b.z, b.w);
        }
    }

    // ---- finalizer-warp setup ----
    const int o = lane & 7;
    float bh = 0.f;
    if (isfin && lane < 24) bh = bhh[(lane >> 3) * H + obase + o];
    float hprev = 0.f;                   // lanes 0..7 carry h for their dim
    const size_t gx_lane_off = (size_t)(lane >> 3) * H + obase + o;
    // poll addresses: lane covers tags {lane, 32+lane, 64+lane, 96+lane}
    const unsigned int* tp0 = &g_tags[(0 * 32 + lane) * TAG_STRIDE];
    const unsigned int* tp1 = &g_tags[(1 * 32 + lane) * TAG_STRIDE];
    const unsigned int* tp2 = &g_tags[(2 * 32 + lane) * TAG_STRIDE];
    const unsigned int* tp3 = &g_tags[(3 * 32 + lane) * TAG_STRIDE];
    unsigned int* mytag = &g_tags[bid * TAG_STRIDE];

    for (int t = 0; t < S; ++t) {
        if (isfin) {
            // prefetch gx (independent of the wait; overlaps the poll)
            float gxv = 0.f;
            if (lane < 24)
                gxv = g_gx[(size_t)t * (3 * H) + gx_lane_off];

            if (t > 0) {
                // poll all 128 producer tags until every one >= t
                unsigned int v0, v1, v2, v3;
                bool ok;
                do {
                    asm volatile("ld.acquire.gpu.global.u32 %0, [%1];"
                                 : "=r"(v0) : "l"(tp0) : "memory");
                    asm volatile("ld.acquire.gpu.global.u32 %0, [%1];"
                                 : "=r"(v1) : "l"(tp1) : "memory");
                    asm volatile("ld.acquire.gpu.global.u32 %0, [%1];"
                                 : "=r"(v2) : "l"(tp2) : "memory");
                    asm volatile("ld.acquire.gpu.global.u32 %0, [%1];"
                                 : "=r"(v3) : "l"(tp3) : "memory");
                    ok = (v0 >= (unsigned)t) & (v1 >= (unsigned)t) &
                         (v2 >= (unsigned)t) & (v3 >= (unsigned)t);
                } while (!__all_sync(0xFFFFFFFFu, ok));
            }
            __syncthreads();   // bar A: release dot warps for step t
            __syncthreads();   // bar B: partials ready

            // finalize: one lane per gate-row (24 lanes)
            float val = 0.f;
            if (lane < 24) {
                const float4* pr = (const float4*)(&partials[lane][0]);
                float4 p0 = pr[0], p1 = pr[1], p2 = pr[2], p3 = pr[3];
                float4 p4 = pr[4], p5 = pr[5], p6 = pr[6], p7 = pr[7];
                float4 q0, q1, q2, q3, r0, r1, f;
                q0.x = p0.x + p1.x; q0.y = p0.y + p1.y; q0.z = p0.z + p1.z; q0.w = p0.w + p1.w;
                q1.x = p2.x + p3.x; q1.y = p2.y + p3.y; q1.z = p2.z + p3.z; q1.w = p2.w + p3.w;
                q2.x = p4.x + p5.x; q2.y = p4.y + p5.y; q2.z = p4.z + p5.z; q2.w = p4.w + p5.w;
                q3.x = p6.x + p7.x; q3.y = p6.y + p7.y; q3.z = p6.z + p7.z; q3.w = p6.w + p7.w;
                r0.x = q0.x + q1.x; r0.y = q0.y + q1.y; r0.z = q0.z + q1.z; r0.w = q0.w + q1.w;
                r1.x = q2.x + q3.x; r1.y = q2.y + q3.y; r1.z = q2.z + q3.z; r1.w = q2.w + q3.w;
                f.x = r0.x + r1.x; f.y = r0.y + r1.y; f.z = r0.z + r1.z; f.w = r0.w + r1.w;
                float s = bh + ((f.x + f.y) + (f.z + f.w));
                val = (lane < 16) ? (s + gxv) : s;   // r/z fold gx; n split
            }
            float v_z  = __shfl_sync(0xFFFFFFFFu, val, o + 8);
            float v_n  = __shfl_sync(0xFFFFFFFFu, val, o + 16);
            float gx_n = __shfl_sync(0xFFFFFFFFu, gxv, o + 16);
            if (lane < 8) {
                float er = __expf(-val);
                float r  = __fdividef(1.f, 1.f + er);
                float ez = __expf(-v_z);
                float z  = __fdividef(1.f, 1.f + ez);
                float a  = gx_n + r * v_n;
                float e2 = __expf(2.f * a);
                float n  = 1.f - __fdividef(2.f, e2 + 1.f);   // tanh(a)
                float hn = z * (hprev - n) + n;               // (1-z)*n + z*h
                hprev = hn;
                out[(size_t)t * H + obase + o] = hn;
            }
            __syncwarp();      // order lanes 0..7's h STGs before the release
            if (lane == 0) {
                asm volatile("st.release.gpu.global.u32 [%0], %1;"
                             :: "l"(mytag), "r"((unsigned)(t + 1)) : "memory");
            }
        } else {
            // ---------------- dot warps ----------------
            __syncthreads();   // bar A: h_{t-1} visible (or t==0)

            unsigned long long h2[4];
            if (t == 0) {
#pragma unroll
                for (int q = 0; q < 4; ++q) h2[q] = 0ULL;
            } else {
                const float4* hp =
                    (const float4*)(out + (size_t)(t - 1) * H + k0);
                float4 a = hp[0], b = hp[1];
                h2[0] = pack2(a.x, a.y);
                h2[1] = pack2(a.z, a.w);
                h2[2] = pack2(b.x, b.y);
                h2[3] = pack2(b.z, b.w);
            }

            float accv[6];
#pragma unroll
            for (int j = 0; j < 6; ++j) {
                unsigned long long acc = 0ULL;
#pragma unroll
                for (int q = 0; q < 4; ++q) acc = ffma2(w2[j][q], h2[q], acc);
                accv[j] = hsum2(acc);
            }
#pragma unroll
            for (int j = 0; j < 6; ++j) {
                accv[j] += __shfl_xor_sync(0xFFFFFFFFu, accv[j], 16);
                accv[j] += __shfl_xor_sync(0xFFFFFFFFu, accv[j], 8);
            }
            if (lane < 8) {
#pragma unroll
                for (int j = 0; j < 6; ++j)
                    partials[g * 6 + j][c * 8 + lane] = accv[j];
            }
            __syncthreads();   // bar B: partials complete
            // next write to partials happens only after bar A of t+1, which
            // the finalizer releases after reading partials -> single buffer.
        }
    }
}

// ---------------------------------------------------------------------------
extern "C" void kernel_launch(void* const* d_in, const int* in_sizes, int n_in,
                              void* d_out, int out_size)
{
    const float* inp  = (const float*)d_in[0];  // [8192, 1024]
    const float* W_ih = (const float*)d_in[1];  // [3072, 1024]
    const float* W_hh = (const float*)d_in[2];  // [3072, 1024]
    const float* b_ih = (const float*)d_in[3];  // [3072]
    const float* b_hh = (const float*)d_in[4];  // [3072]
    float* out = (float*)d_out;                 // [8192, 1024]

    // 1) gx = inp @ W_ih^T + b_ih (block (0,0) also clears g_tags)
    dim3 ggrid(3072 / 128, S / 128);
    gemm_gx_kernel<<<ggrid, 256>>>(inp, W_ih, b_ih);

    // 2) persistent sequential GRU scan (one wave of 128 CTAs)
    gru_scan_kernel<<<NSM, SCAN_THREADS>>>(W_hh, b_hh, out);
}

// round 6
// speedup vs baseline: 1.6867x; 1.3340x over previous
#include <cuda_runtime.h>
#include <cstdint>

#define S 8192
#define H 1024
#define NSM 128
#define SCAN_THREADS 544   // 16 dot-warps + finalizer warp 16 (highest wid)

// Scratch: input-side gate projections gx[S][3H].
__device__ float g_gx[(size_t)S * 3 * H];
// h-exchange lines, double buffered: [slot][producer][16 floats]
//   floats 0..7 = h values, word 8 = monotone tag (uint), rest pad. 64B/line.
__device__ __align__(64) float g_hline[2 * NSM * 16];

// ---------------------------------------------------------------------------
// packed fp32x2 helpers (sm_103a FFMA2 path)
// ---------------------------------------------------------------------------
__device__ __forceinline__ unsigned long long pack2(float lo, float hi) {
    unsigned long long r;
    asm("mov.b64 %0, {%1, %2};" : "=l"(r) : "f"(lo), "f"(hi));
    return r;
}
__device__ __forceinline__ unsigned long long ffma2(unsigned long long a,
                                                    unsigned long long b,
                                                    unsigned long long c) {
    unsigned long long d;
    asm("fma.rn.f32x2 %0, %1, %2, %3;" : "=l"(d) : "l"(a), "l"(b), "l"(c));
    return d;
}
__device__ __forceinline__ float hsum2(unsigned long long a) {
    float lo, hi;
    asm("mov.b64 {%0, %1}, %2;" : "=f"(lo), "=f"(hi) : "l"(a));
    return lo + hi;
}

// ---------------------------------------------------------------------------
// Kernel 1: gx = inp @ W_ih^T + b_ih  (fp32 GEMM, 128x128x16 tiles, FFMA2)
// Block (0,0) also clears the h-line buffer (tags) for this graph replay.
// ---------------------------------------------------------------------------
__global__ __launch_bounds__(256) void gemm_gx_kernel(
    const float* __restrict__ A,
    const float* __restrict__ Wih,
    const float* __restrict__ bih)
{
    __shared__ __align__(16) float As[16][132];
    __shared__ __align__(16) float Bs[16][132];

    const int tid = threadIdx.x;
    if (blockIdx.x == 0 && blockIdx.y == 0) {
        // 2*128*16 floats = 4096 floats; 256 threads x 16 floats each
        float4 z = make_float4(0.f, 0.f, 0.f, 0.f);
        float4* dst = (float4*)(g_hline + (size_t)tid * 16);
        dst[0] = z; dst[1] = z; dst[2] = z; dst[3] = z;
    }

    const int m0 = blockIdx.y * 128;
    const int n0 = blockIdx.x * 128;
    const int tx = tid & 15;
    const int ty = tid >> 4;

    unsigned long long acc2[8][4];
#pragma unroll
    for (int i = 0; i < 8; ++i)
#pragma unroll
        for (int q = 0; q < 4; ++q) acc2[i][q] = 0ULL;

    for (int kt = 0; kt < 1024; kt += 16) {
#pragma unroll
        for (int r = 0; r < 2; ++r) {
            int idx = tid + r * 256;
            int row = idx >> 2;
            int kq  = idx & 3;
            float4 v = *(const float4*)(A + (size_t)(m0 + row) * 1024 + kt + kq * 4);
            As[kq * 4 + 0][row] = v.x;
            As[kq * 4 + 1][row] = v.y;
            As[kq * 4 + 2][row] = v.z;
            As[kq * 4 + 3][row] = v.w;
        }
#pragma unroll
        for (int r = 0; r < 2; ++r) {
            int idx = tid + r * 256;
            int n  = idx >> 2;
            int kq = idx & 3;
            float4 v = *(const float4*)(Wih + (size_t)(n0 + n) * 1024 + kt + kq * 4);
            Bs[kq * 4 + 0][n] = v.x;
            Bs[kq * 4 + 1][n] = v.y;
            Bs[kq * 4 + 2][n] = v.z;
            Bs[kq * 4 + 3][n] = v.w;
        }
        __syncthreads();

#pragma unroll
        for (int k = 0; k < 16; ++k) {
            float4 b0 = *(const float4*)&Bs[k][tx * 8];
            float4 b1 = *(const float4*)&Bs[k][tx * 8 + 4];
            unsigned long long rb2[4];
            rb2[0] = pack2(b0.x, b0.y);
            rb2[1] = pack2(b0.z, b0.w);
            rb2[2] = pack2(b1.x, b1.y);
            rb2[3] = pack2(b1.z, b1.w);
#pragma unroll
            for (int i = 0; i < 8; ++i) {
                float a = As[k][ty * 8 + i];
                unsigned long long a2 = pack2(a, a);
#pragma unroll
                for (int q = 0; q < 4; ++q)
                    acc2[i][q] = ffma2(a2, rb2[q], acc2[i][q]);
            }
        }
        __syncthreads();
    }

#pragma unroll
    for (int i = 0; i < 8; ++i) {
        size_t rowoff = (size_t)(m0 + ty * 8 + i) * 3072 + n0 + tx * 8;
#pragma unroll
        for (int jq = 0; jq < 2; ++jq) {
            float lo0, hi0, lo1, hi1;
            asm("mov.b64 {%0, %1}, %2;" : "=f"(lo0), "=f"(hi0) : "l"(acc2[i][jq * 2 + 0]));
            asm("mov.b64 {%0, %1}, %2;" : "=f"(lo1), "=f"(hi1) : "l"(acc2[i][jq * 2 + 1]));
            float4 v;
            v.x = lo0 + bih[n0 + tx * 8 + jq * 4 + 0];
            v.y = hi0 + bih[n0 + tx * 8 + jq * 4 + 1];
            v.z = lo1 + bih[n0 + tx * 8 + jq * 4 + 2];
            v.w = hi1 + bih[n0 + tx * 8 + jq * 4 + 3];
            *(float4*)(g_gx + rowoff + jq * 4) = v;
        }
    }
}

// ---------------------------------------------------------------------------
// Kernel 2: persistent GRU scan. 128 CTAs (one per SM), 544 threads.
//
// Warps 0..15 (dot warps): chunk c = warp>>2 (k-range c*256..+255), row-group
//   g = warp&3 (6 gate-rows each). W_hh slice register-resident (f32x2).
//   The g==0 warp of each chunk polls its 32 producers' fused h+tag lines
//   (lane <-> producer 1:1), pulls h with __ldcg from the just-hot line, and
//   relays it to siblings via smem + a per-chunk named barrier. No spinning
//   siblings, no global flag word, no wait-for-all-128 before work starts.
// Warp 16 (finalizer, highest wid = arbiter priority): waits one
//   __syncthreads for partials, finalizes gates (24 parallel sigmoids),
//   writes d_out, and publishes its h+tag line (stcg data + st.release tag).
//
// h lines are double-buffered on t&1; cross-CTA skew is bounded by 1 step by
// construction, so 2 slots are race-free. partials double-buffered on t&1.
// ---------------------------------------------------------------------------
__global__ __launch_bounds__(SCAN_THREADS, 1) void gru_scan_kernel(
    const float* __restrict__ Whh,
    const float* __restrict__ bhh,
    float* __restrict__ out)
{
    const int tid  = threadIdx.x;
    const int warp = tid >> 5;
    const int lane = tid & 31;
    const int bid  = blockIdx.x;
    const int obase = bid * 8;

    __shared__ __align__(16) float s_h[4][256];        // per-chunk h relay
    __shared__ __align__(16) float partials[2][24][36];

    const bool isfin = (warp == 16);
    const int c = warp >> 2;             // k-chunk (0..3) for dot warps
    const int g = warp & 3;              // row-group (0..3)
    const int k0 = c * 256 + lane * 8;
    const int p  = c * 32 + lane;        // producer this lane polls (g==0)

    // ---- dot-warp setup: 6 gate-rows x 8 cols of W_hh, packed f32x2 ----
    unsigned long long w2[6][4];
    if (!isfin) {
#pragma unroll
        for (int j = 0; j < 6; ++j) {
            int gr  = g * 6 + j;                          // 0..23
            int row = (gr >> 3) * H + obase + (gr & 7);   // gate*H + out idx
            const float4* pw = (const float4*)(Whh + (size_t)row * H + k0);
            float4 a = pw[0], b = pw[1];
            w2[j][0] = pack2(a.x, a.y);
            w2[j][1] = pack2(a.z, a.w);
            w2[j][2] = pack2(b.x, b.y);
            w2[j][3] = pack2(b.z, b.w);
        }
    }

    // ---- finalizer setup ----
    const int o = lane & 7;
    float bh = 0.f;
    if (isfin && lane < 24) bh = bhh[(lane >> 3) * H + obase + o];
    float hprev = 0.f;                   // lanes 0..7 carry h for their dim
    const size_t gx_lane_off = (size_t)(lane >> 3) * H + obase + o;

    for (int t = 0; t < S; ++t) {
        const int buf = t & 1;

        if (isfin) {
            // prefetch gx (overlaps dot warps' work for this step)
            float gxv = 0.f;
            if (lane < 24)
                gxv = g_gx[(size_t)t * (3 * H) + gx_lane_off];

            __syncthreads();   // partials[buf] for step t are complete

            float s = 0.f;
            if (lane < 24) {
                const float4* pr = (const float4*)(&partials[buf][lane][0]);
                float4 p0 = pr[0], p1 = pr[1], p2 = pr[2], p3 = pr[3];
                float4 p4 = pr[4], p5 = pr[5], p6 = pr[6], p7 = pr[7];
                float4 q0, q1, q2, q3, r0, r1, f;
                q0.x = p0.x + p1.x; q0.y = p0.y + p1.y; q0.z = p0.z + p1.z; q0.w = p0.w + p1.w;
                q1.x = p2.x + p3.x; q1.y = p2.y + p3.y; q1.z = p2.z + p3.z; q1.w = p2.w + p3.w;
                q2.x = p4.x + p5.x; q2.y = p4.y + p5.y; q2.z = p4.z + p5.z; q2.w = p4.w + p5.w;
                q3.x = p6.x + p7.x; q3.y = p6.y + p7.y; q3.z = p6.z + p7.z; q3.w = p6.w + p7.w;
                r0.x = q0.x + q1.x; r0.y = q0.y + q1.y; r0.z = q0.z + q1.z; r0.w = q0.w + q1.w;
                r1.x = q2.x + q3.x; r1.y = q2.y + q3.y; r1.z = q2.z + q3.z; r1.w = q2.w + q3.w;
                f.x = r0.x + r1.x; f.y = r0.y + r1.y; f.z = r0.z + r1.z; f.w = r0.w + r1.w;
                s = bh + ((f.x + f.y) + (f.z + f.w));
            }
            // lanes 0..15: pre-activation of r/z includes gx; lanes 16..23
            // keep hidden n-side and gx_n separate (r gates only hidden part)
            float val = s + ((lane < 16) ? gxv : 0.f);
            float sig = __fdividef(1.f, 1.f + __expf(-val));  // 24 parallel
            float v_n  = __shfl_sync(0xFFFFFFFFu, s,   o + 16);
            float gx_n = __shfl_sync(0xFFFFFFFFu, gxv, o + 16);
            float zz   = __shfl_sync(0xFFFFFFFFu, sig, o + 8);
            if (lane < 8) {
                float r  = sig;
                float a  = gx_n + r * v_n;
                float e2 = __expf(2.f * a);
                float n  = 1.f - __fdividef(2.f, e2 + 1.f);   // tanh(a)
                float hn = zz * (hprev - n) + n;              // (1-z)*n + z*h
                hprev = hn;
                out[(size_t)t * H + obase + o] = hn;
                __stcg(&g_hline[((size_t)buf * NSM + bid) * 16 + o], hn);
            }
            __syncwarp();      // order the 8 h stores before the tag release
            if (lane == 0) {
                unsigned int* tagp =
                    (unsigned int*)g_hline + ((size_t)buf * NSM + bid) * 16 + 8;
                asm volatile("st.release.gpu.global.u32 [%0], %1;"
                             :: "l"(tagp), "r"((unsigned)(t + 1)) : "memory");
            }
        } else {
            // ---------------- dot warps ----------------
            unsigned long long h2[4];
            if (t == 0) {
#pragma unroll
                for (int q = 0; q < 4; ++q) h2[q] = 0ULL;
            } else {
                const int slot = (t - 1) & 1;
                if (g == 0) {
                    // poll producer p's tag (fused in its h line)
                    const unsigned int* tagp =
                        (const unsigned int*)g_hline +
                        ((size_t)slot * NSM + p) * 16 + 8;
                    unsigned int v;
                    do {
                        asm volatile("ld.acquire.gpu.global.u32 %0, [%1];"
                                     : "=r"(v) : "l"(tagp) : "memory");
                    } while (__any_sync(0xFFFFFFFFu, v < (unsigned)t));
                    // h data: same line, now hot in L2 (bypass L1)
                    const float4* dp =
                        (const float4*)(g_hline + ((size_t)slot * NSM + p) * 16);
                    float4 a = __ldcg(dp);
                    float4 b = __ldcg(dp + 1);
                    *(float4*)&s_h[c][lane * 8]     = a;
                    *(float4*)&s_h[c][lane * 8 + 4] = b;
                    h2[0] = pack2(a.x, a.y);
                    h2[1] = pack2(a.z, a.w);
                    h2[2] = pack2(b.x, b.y);
                    h2[3] = pack2(b.z, b.w);
                    asm volatile("bar.sync %0, %1;" :: "r"(c + 1), "r"(128)
                                 : "memory");
                } else {
                    asm volatile("bar.sync %0, %1;" :: "r"(c + 1), "r"(128)
                                 : "memory");
                    float4 a = *(const float4*)&s_h[c][lane * 8];
                    float4 b = *(const float4*)&s_h[c][lane * 8 + 4];
                    h2[0] = pack2(a.x, a.y);
                    h2[1] = pack2(a.z, a.w);
                    h2[2] = pack2(b.x, b.y);
                    h2[3] = pack2(b.z, b.w);
                }
            }

            float accv[6];
#pragma unroll
            for (int j = 0; j < 6; ++j) {
                unsigned long long acc = 0ULL;
#pragma unroll
                for (int q = 0; q < 4; ++q) acc = ffma2(w2[j][q], h2[q], acc);
                accv[j] = hsum2(acc);
            }
#pragma unroll
            for (int j = 0; j < 6; ++j) {
                accv[j] += __shfl_xor_sync(0xFFFFFFFFu, accv[j], 16);
                accv[j] += __shfl_xor_sync(0xFFFFFFFFu, accv[j], 8);
            }
            if (lane < 8) {
#pragma unroll
                for (int j = 0; j < 6; ++j)
                    partials[buf][g * 6 + j][c * 8 + lane] = accv[j];
            }
            __syncthreads();   // release finalizer for step t; dot warps
                               // proceed straight to step t+1's poll
        }
    }
}

// ---------------------------------------------------------------------------
extern "C" void kernel_launch(void* const* d_in, const int* in_sizes, int n_in,
                              void* d_out, int out_size)
{
    const float* inp  = (const float*)d_in[0];  // [8192, 1024]
    const float* W_ih = (const float*)d_in[1];  // [3072, 1024]
    const float* W_hh = (const float*)d_in[2];  // [3072, 1024]
    const float* b_ih = (const float*)d_in[3];  // [3072]
    const float* b_hh = (const float*)d_in[4];  // [3072]
    float* out = (float*)d_out;                 // [8192, 1024]

    // 1) gx = inp @ W_ih^T + b_ih (block (0,0) also clears g_hline tags)
    dim3 ggrid(3072 / 128, S / 128);
    gemm_gx_kernel<<<ggrid, 256>>>(inp, W_ih, b_ih);

    // 2) persistent sequential GRU scan (one wave of 128 CTAs)
    gru_scan_kernel<<<NSM, SCAN_THREADS>>>(W_hh, b_hh, out);
}